// round 16
// baseline (speedup 1.0000x reference)
#include <cuda_runtime.h>

#define B      384
#define DIM    1024
#define TS     64                // gram tile size
#define SPLITK 8
#define KPB    (DIM / SPLITK)    // 128 k per gram block
#define NIT    (KPB / 32)        // 4 iterations of k=32

typedef unsigned long long ull;

// Scratch in device globals (no allocations allowed).
__device__ float  g_G[B * B];            // Gram matrix (RED-accumulated)
__device__ float  g_sq[B];               // diag(G)
__device__ int    g_lab[B];              // labels normalized to int32
__device__ double g_ptot[B];             // per-anchor loss partials
__device__ ull    g_pcnt[B];             // per-anchor triplet counts
__device__ unsigned int g_done;

// Staggered smem layout (float2/ull units): row j (0..63), 16 units per row,
// stride 17, extra bump every 16 rows. Row set {4tx+c} maps to bank-pairs
// (c + 4(tx&3) + (tx>>2)) mod 16 -> all 16 distinct: conflict-free LDS.64.
__device__ __forceinline__ int soff64(int j) {
    return j * 17 + (j >> 4);
}

// Packed dual fp32 FMA (SASS FFMA2) — only reachable via PTX.
__device__ __forceinline__ void ffma2(ull& acc, ull a, ull b) {
    asm("fma.rn.f32x2 %0, %1, %2, %0;" : "+l"(acc) : "l"(a), "l"(b));
}

__device__ __forceinline__ float unpack_sum(ull v) {
    float lo = __uint_as_float((unsigned)(v & 0xffffffffull));
    float hi = __uint_as_float((unsigned)(v >> 32));
    return lo + hi;   // even-k partial + odd-k partial
}

// ---------------------------------------------------------------------------
// Kernel 0: zero the accumulation targets. 384 blocks x 384 threads = one
// float of g_G per thread; block 0 also clears g_sq and g_done.
// ---------------------------------------------------------------------------
__global__ void __launch_bounds__(B)
k_zero() {
    g_G[blockIdx.x * B + threadIdx.x] = 0.f;
    if (blockIdx.x == 0) {
        g_sq[threadIdx.x] = 0.f;
        if (threadIdx.x == 0) g_done = 0u;
    }
}

// ---------------------------------------------------------------------------
// Kernel 1: split-K Gram, 64x64 tiles, 4x4 FFMA2 micro-tile, RED epilogue.
// grid (6,6,8) = 288 blocks, 256 threads, 2 blocks/SM (single wave).
// ---------------------------------------------------------------------------
__global__ void __launch_bounds__(256, 2)
k_gram(const float* __restrict__ E, const void* __restrict__ labp) {
    __shared__ float2 SA[2][1090];
    __shared__ float2 SB[2][1090];

    const int tid = threadIdx.x;
    const int btx = blockIdx.x, bty = blockIdx.y, kz = blockIdx.z;
    const int row0 = bty * TS, col0 = btx * TS;

    const int tx = tid & 15, ty = tid >> 4;
    const int li = tid >> 2;                   // loader row 0..63
    const int lq = tid & 3;                    // loader quarter (8 floats)
    const float* Ea = E + (size_t)(row0 + li) * DIM + kz * KPB + lq * 8;
    const float* Eb = E + (size_t)(col0 + li) * DIM + kz * KPB + lq * 8;

    const int st0 = soff64(li) + lq * 4;       // ull-unit store base
    int aoff[4], boff[4];
#pragma unroll
    for (int r = 0; r < 4; r++) {
        aoff[r] = soff64(4 * ty + r);
        boff[r] = soff64(4 * tx + r);
    }

    ull acc[4][4];
#pragma unroll
    for (int r = 0; r < 4; r++)
#pragma unroll
        for (int c = 0; c < 4; c++) acc[r][c] = 0ull;

    // 2-deep register prefetch: tile i lives in slot i&1 (2 float4 / panel).
    float4 ra[2][2], rb[2][2];
    ra[0][0] = *(const float4*)(Ea);       ra[0][1] = *(const float4*)(Ea + 4);
    rb[0][0] = *(const float4*)(Eb);       rb[0][1] = *(const float4*)(Eb + 4);
    ra[1][0] = *(const float4*)(Ea + 32);  ra[1][1] = *(const float4*)(Ea + 36);
    rb[1][0] = *(const float4*)(Eb + 32);  rb[1][1] = *(const float4*)(Eb + 36);

    SA[0][st0]     = make_float2(ra[0][0].x, ra[0][0].y);
    SA[0][st0 + 1] = make_float2(ra[0][0].z, ra[0][0].w);
    SA[0][st0 + 2] = make_float2(ra[0][1].x, ra[0][1].y);
    SA[0][st0 + 3] = make_float2(ra[0][1].z, ra[0][1].w);
    SB[0][st0]     = make_float2(rb[0][0].x, rb[0][0].y);
    SB[0][st0 + 1] = make_float2(rb[0][0].z, rb[0][0].w);
    SB[0][st0 + 2] = make_float2(rb[0][1].x, rb[0][1].y);
    SB[0][st0 + 3] = make_float2(rb[0][1].z, rb[0][1].w);
    __syncthreads();

    for (int it = 0; it < NIT; it++) {
        if (it + 1 < NIT) {                 // stage tile it+1 into other buffer
            const int nb = (it + 1) & 1;
            SA[nb][st0]     = make_float2(ra[nb][0].x, ra[nb][0].y);
            SA[nb][st0 + 1] = make_float2(ra[nb][0].z, ra[nb][0].w);
            SA[nb][st0 + 2] = make_float2(ra[nb][1].x, ra[nb][1].y);
            SA[nb][st0 + 3] = make_float2(ra[nb][1].z, ra[nb][1].w);
            SB[nb][st0]     = make_float2(rb[nb][0].x, rb[nb][0].y);
            SB[nb][st0 + 1] = make_float2(rb[nb][0].z, rb[nb][0].w);
            SB[nb][st0 + 2] = make_float2(rb[nb][1].x, rb[nb][1].y);
            SB[nb][st0 + 3] = make_float2(rb[nb][1].z, rb[nb][1].w);
        }
        if (it + 2 < NIT) {                 // LDG tile it+2 into freed slot
            const int s = it & 1;
            ra[s][0] = *(const float4*)(Ea + (it + 2) * 32);
            ra[s][1] = *(const float4*)(Ea + (it + 2) * 32 + 4);
            rb[s][0] = *(const float4*)(Eb + (it + 2) * 32);
            rb[s][1] = *(const float4*)(Eb + (it + 2) * 32 + 4);
        }
        const ull* SAu = (const ull*)SA[it & 1];
        const ull* SBu = (const ull*)SB[it & 1];
#pragma unroll
        for (int kk = 0; kk < 16; kk++) {
            ull av[4], bv[4];
#pragma unroll
            for (int r = 0; r < 4; r++) av[r] = SAu[aoff[r] + kk];
#pragma unroll
            for (int c = 0; c < 4; c++) bv[c] = SBu[boff[c] + kk];
#pragma unroll
            for (int r = 0; r < 4; r++)
#pragma unroll
                for (int c = 0; c < 4; c++)
                    ffma2(acc[r][c], av[r], bv[c]);
        }
        __syncthreads();
    }

    // Epilogue: RED-accumulate into the single g_G (fire-and-forget, spread
    // addresses). Diagonal contributes to g_sq the same way.
#pragma unroll
    for (int r = 0; r < 4; r++) {
        const int gr = row0 + 4 * ty + r;
        float* gp = g_G + (size_t)gr * B + col0 + 4 * tx;
        const float v0 = unpack_sum(acc[r][0]);
        const float v1 = unpack_sum(acc[r][1]);
        const float v2 = unpack_sum(acc[r][2]);
        const float v3 = unpack_sum(acc[r][3]);
        atomicAdd(gp + 0, v0);
        atomicAdd(gp + 1, v1);
        atomicAdd(gp + 2, v2);
        atomicAdd(gp + 3, v3);
        if (btx == bty && tx == ty) {
            float dg = (r == 0) ? v0 : (r == 1) ? v1 : (r == 2) ? v2 : v3;
            atomicAdd(&g_sq[gr], dg);       // diag partial: acc[r][r]
        }
    }

    // --- Label parse (block (0,0,0) only). Detect int64 vs int32 on the
    // first 1536 bytes: non-negative LE int64 => odd int32 words all zero.
    if (btx == 0 && bty == 0 && kz == 0) {
        const int* p32 = (const int*)labp;
        int ok = 1, ap = 0;
        for (int w = tid; w < B; w += 256) {
            int v = p32[w];
            if (w & 1) { if (v != 0) ok = 0; }
            else       { if (v > 0)  ap = 1; }
        }
        const int allz = __syncthreads_and(ok);
        const int anyp = __syncthreads_or(ap);
        const int is64 = allz && anyp;
        for (int j = tid; j < B; j += 256)
            g_lab[j] = is64 ? (int)((const long long*)labp)[j] : p32[j];
    }
}

// ---------------------------------------------------------------------------
// Kernel 2: triplet loss. One block per anchor, 384 threads. Reads the single
// accumulated g_G. Per-block partials to distinct addresses; last block
// parallel-reduces.  D[a,j]-D[a,n] = (sq_j-2G[a,j]) - (sq_n-2G[a,n]).
// ---------------------------------------------------------------------------
__global__ void __launch_bounds__(B)
k_loss(float* __restrict__ out, int out_size) {
    __shared__ float  P[B];
    __shared__ int    s_npos;
    __shared__ double s_red[12];
    __shared__ ull    s_redc[12];
    __shared__ int    s_last;

    const int a = blockIdx.x;
    const int t = threadIdx.x;
    const int lane = t & 31, wid = t >> 5;

    // Front-batch the few independent loads.
    const float gv = g_G[a * B + t];
    const float sq = g_sq[t];
    const int   lt = g_lab[t];
    const int   la = g_lab[a];          // warp-uniform broadcast load

    if (t == 0) s_npos = 0;
    __syncthreads();

    const float d = sq - 2.0f * gv;
    const int ispos = (t > a) && (lt == la);

    // Warp-aggregated compaction of positives into P.
    unsigned m = __ballot_sync(0xffffffffu, ispos);
    if (m) {
        int base = 0;
        if (lane == 0) base = atomicAdd(&s_npos, __popc(m));
        base = __shfl_sync(0xffffffffu, base, 0);
        if (ispos) P[base + __popc(m & ((1u << lane) - 1u))] = d;
    }
    const int is_neg = (lt != la);
    const int nneg = __syncthreads_count(is_neg);   // publishes P / s_npos
    const int npos = s_npos;

    float acc = 0.f;
    if (is_neg && npos > 0) {
        const float cadd = 1.0f - d;    // margin - D[a,n]
        for (int q = 0; q < npos; q++) {
            float v = P[q] + cadd;
            acc += (v > 0.f) ? v : 0.f;
        }
    }

#pragma unroll
    for (int off = 16; off > 0; off >>= 1)
        acc += __shfl_down_sync(0xffffffffu, acc, off);
    if (lane == 0) s_red[wid] = (double)acc;
    __syncthreads();

    if (t == 0) {
        double tot = 0.0;
        for (int i = 0; i < 12; i++) tot += s_red[i];
        g_ptot[a] = tot;                              // distinct addresses:
        g_pcnt[a] = (ull)npos * (ull)nneg;            // plain STG, no atomics
        __threadfence();
        s_last = (atomicInc(&g_done, 0xffffffffu) == (unsigned)(B - 1));
    }
    __syncthreads();

    // --- Last block: parallel reduce the 384 partials and finalize. --------
    if (s_last) {
        double v = g_ptot[t];
        ull    c = g_pcnt[t];
#pragma unroll
        for (int off = 16; off > 0; off >>= 1) {
            v += __shfl_down_sync(0xffffffffu, v, off);
            c += __shfl_down_sync(0xffffffffu, c, off);
        }
        if (lane == 0) { s_red[wid] = v; s_redc[wid] = c; }
        __syncthreads();
        if (t == 0) {
            double tot = 0.0; ull cnt = 0ull;
            for (int i = 0; i < 12; i++) { tot += s_red[i]; cnt += s_redc[i]; }
            double mean = (cnt > 0) ? (tot / (double)cnt) : 0.0;
            if (out_size >= 1) out[0] = (float)mean;
            if (out_size >= 2) out[1] = (float)cnt;
        }
    }
}

// Nop: pads the per-replay launch pattern to period 4 so ncu's "-s 5 -c 1"
// lands on k_gram (launch #6 = 2nd kernel of the 2nd replay) instead of
// always re-profiling k_loss.
__global__ void k_nop() {}

extern "C" void kernel_launch(void* const* d_in, const int* in_sizes, int n_in,
                              void* d_out, int out_size) {
    const float* E = (const float*)d_in[0];
    const void* labels = d_in[1];
    float* out = (float*)d_out;

    k_zero<<<B, B>>>();
    k_gram<<<dim3(6, 6, SPLITK), 256>>>(E, labels);
    k_loss<<<B, B>>>(out, out_size);
    k_nop<<<1, 1>>>();
}